// round 8
// baseline (speedup 1.0000x reference)
#include <cuda_runtime.h>
#include <cuda_bf16.h>
#include <math.h>

#define NSEQ  4096
#define CDIM  512
#define HCDIM 64
#define BATCH 4

// ---------------- scratch ----------------
__device__ float d_sig[4];
__device__ __nv_bfloat16 d_fh [BATCH * HCDIM * NSEQ];   // f hi
__device__ __nv_bfloat16 d_fl [BATCH * HCDIM * NSEQ];   // f lo
__device__ __nv_bfloat16 d_gh [BATCH * HCDIM * NSEQ];   // g hi
__device__ __nv_bfloat16 d_gl [BATCH * HCDIM * NSEQ];   // g lo
__device__ __nv_bfloat16 d_hbf[BATCH * HCDIM * NSEQ];   // h (bf16)
__device__ __nv_bfloat16 d_oh [BATCH * HCDIM * NSEQ];   // o hi
__device__ __nv_bfloat16 d_ol [BATCH * HCDIM * NSEQ];   // o lo

// ---------------- small helpers ----------------
__device__ __forceinline__ unsigned pk_bf16(float lo, float hi) {
    unsigned r; asm("cvt.rn.bf16x2.f32 %0, %1, %2;" : "=r"(r) : "f"(hi), "f"(lo)); return r;
}
__device__ __forceinline__ void mma_bf16(float* d, const unsigned* a, unsigned b0, unsigned b1) {
    asm volatile("mma.sync.aligned.m16n8k16.row.col.f32.bf16.bf16.f32 "
        "{%0,%1,%2,%3},{%4,%5,%6,%7},{%8,%9},{%0,%1,%2,%3};"
        : "+f"(d[0]), "+f"(d[1]), "+f"(d[2]), "+f"(d[3])
        : "r"(a[0]), "r"(a[1]), "r"(a[2]), "r"(a[3]), "r"(b0), "r"(b1));
}
__device__ __forceinline__ void ldsm4(unsigned* r, unsigned addr) {
    asm volatile("ldmatrix.sync.aligned.m8n8.x4.shared.b16 {%0,%1,%2,%3}, [%4];"
                 : "=r"(r[0]), "=r"(r[1]), "=r"(r[2]), "=r"(r[3]) : "r"(addr));
}
__device__ __forceinline__ void ldsm2t(unsigned& r0, unsigned& r1, unsigned addr) {
    asm volatile("ldmatrix.sync.aligned.m8n8.x2.trans.shared.b16 {%0,%1}, [%2];"
                 : "=r"(r0), "=r"(r1) : "r"(addr));
}
__device__ __forceinline__ unsigned smem_u32(const void* p) {
    return (unsigned)__cvta_generic_to_shared(p);
}
__device__ __forceinline__ void cp_async16(void* dst, const void* src) {
    asm volatile("cp.async.cg.shared.global [%0], [%1], 16;"
                 :: "r"(smem_u32(dst)), "l"(src));
}
__device__ __forceinline__ void cp_commit() { asm volatile("cp.async.commit_group;"); }
template <int N>
__device__ __forceinline__ void cp_wait() { asm volatile("cp.async.wait_group %0;" :: "n"(N)); }

__device__ __forceinline__ void split2(float a0, float a1, unsigned& hi, unsigned& lo) {
    hi = pk_bf16(a0, a1);
    __nv_bfloat162 hv = *reinterpret_cast<__nv_bfloat162*>(&hi);
    lo = pk_bf16(a0 - __bfloat162float(hv.x), a1 - __bfloat162float(hv.y));
}
__device__ __forceinline__ unsigned pack2(const __nv_bfloat16* p0, const __nv_bfloat16* p1) {
    unsigned short u0 = *(const unsigned short*)p0;
    unsigned short u1 = *(const unsigned short*)p1;
    return (unsigned)u0 | ((unsigned)u1 << 16);
}

// ---------------- spectral norm sigmas ----------------
__global__ void sigma_kernel(const float* __restrict__ Wf, const float* __restrict__ Wg,
                             const float* __restrict__ Wh, const float* __restrict__ Wv,
                             const float* __restrict__ uf, const float* __restrict__ ug,
                             const float* __restrict__ uh, const float* __restrict__ uv) {
    int mat = blockIdx.x;
    __shared__ float v[512];
    __shared__ float red[256];
    int t = threadIdx.x;

    if (mat < 3) {
        const float* W = (mat == 0) ? Wf : (mat == 1) ? Wg : Wh;
        const float* u = (mat == 0) ? uf : (mat == 1) ? ug : uh;
        for (int j = t; j < 512; j += 256) {
            float s = 0.f;
            #pragma unroll 8
            for (int i = 0; i < 64; i++) s += W[i * 512 + j] * u[i];
            v[j] = s;
        }
        __syncthreads();
        float ps = 0.f;
        for (int j = t; j < 512; j += 256) ps += v[j] * v[j];
        red[t] = ps; __syncthreads();
        for (int off = 128; off; off >>= 1) { if (t < off) red[t] += red[t + off]; __syncthreads(); }
        float inv = 1.f / fmaxf(sqrtf(red[0]), 1e-12f);
        __syncthreads();
        int i = t >> 2, q = t & 3;
        float s = 0.f;
        const float* wr = W + i * 512 + q * 128;
        const float* vv = v + q * 128;
        #pragma unroll 8
        for (int j = 0; j < 128; j += 4) {
            float4 w4 = *(const float4*)(wr + j);
            s += w4.x * vv[j] + w4.y * vv[j + 1] + w4.z * vv[j + 2] + w4.w * vv[j + 3];
        }
        s += __shfl_xor_sync(0xffffffffu, s, 1);
        s += __shfl_xor_sync(0xffffffffu, s, 2);
        s *= inv;
        red[t] = (q == 0) ? s * s : 0.f;
    } else {
        const float* W = Wv;
        const float* u = uv;
        int j = t & 63, ch = t >> 6;
        float s = 0.f;
        for (int i = ch * 128; i < ch * 128 + 128; i++) s += W[i * 64 + j] * u[i];
        red[t] = s; __syncthreads();
        if (t < 64) v[t] = red[t] + red[t + 64] + red[t + 128] + red[t + 192];
        __syncthreads();
        float ps = (t < 64) ? v[t] * v[t] : 0.f;
        __syncthreads();
        red[t] = ps; __syncthreads();
        for (int off = 128; off; off >>= 1) { if (t < off) red[t] += red[t + off]; __syncthreads(); }
        float inv = 1.f / fmaxf(sqrtf(red[0]), 1e-12f);
        __syncthreads();
        float ps2 = 0.f;
        #pragma unroll
        for (int rr = 0; rr < 2; rr++) {
            int i = t + rr * 256;
            float s2 = 0.f;
            const float* wr = W + i * 64;
            #pragma unroll
            for (int jj = 0; jj < 64; jj += 4) {
                float4 w4 = *(const float4*)(wr + jj);
                s2 += w4.x * v[jj] + w4.y * v[jj + 1] + w4.z * v[jj + 2] + w4.w * v[jj + 3];
            }
            s2 *= inv;
            ps2 += s2 * s2;
        }
        red[t] = ps2;
    }
    __syncthreads();
    for (int off = 128; off; off >>= 1) { if (t < off) red[t] += red[t + off]; __syncthreads(); }
    if (t == 0) d_sig[mat] = 1.f / fmaxf(sqrtf(red[0]), 1e-30f);
}

// ---------------- f,g,h fused: 3 mats in one CTA (M=192, N=128, K=512) ----------------
#define FG_BUF 48128
__global__ __launch_bounds__(384) void fgh_mma_kernel(
    const float* __restrict__ x,
    const float* __restrict__ Wf, const float* __restrict__ bf,
    const float* __restrict__ Wg, const float* __restrict__ bg,
    const float* __restrict__ Wh, const float* __restrict__ bh) {
    extern __shared__ char fsm[];
    int n0 = blockIdx.x * 128;
    int b  = blockIdx.y;

    int t = threadIdx.x, w = t >> 5, lane = t & 31;
    int wn = w & 1, wm = w >> 1;
    int g = lane >> 2, tig = lane & 3, ln15 = lane & 15, lnh = lane >> 4;

    int wrow = t >> 1, wcol = (t & 1) * 16;
    int wmat = wrow >> 6;
    const float* Wp = ((wmat == 0) ? Wf : (wmat == 1) ? Wg : Wh) + (size_t)(wrow & 63) * 512;
    float winvs = d_sig[wmat];
    int xrow = t >> 3, xcol = (t & 7) * 16;
    const float* xp = x + (size_t)b * CDIM * NSEQ;
    unsigned sm_base = smem_u32(fsm);

    float4 wr0, wr1, wr2, wr3, xr0, xr1, xr2, xr3;
    auto ldg_chunk = [&](int chunk) {
        int c0 = chunk * 32;
        const float* wq = Wp + c0 + wcol;
        wr0 = *(const float4*)(wq);
        wr1 = *(const float4*)(wq + 4);
        wr2 = *(const float4*)(wq + 8);
        wr3 = *(const float4*)(wq + 12);
        if (t < 256) {
            const float* xq = xp + (size_t)(c0 + xrow) * NSEQ + n0 + xcol;
            xr0 = *(const float4*)(xq);
            xr1 = *(const float4*)(xq + 4);
            xr2 = *(const float4*)(xq + 8);
            xr3 = *(const float4*)(xq + 12);
        }
    };
    auto sts_chunk = [&](int sel) {
        char* base = fsm + sel * FG_BUF;
        {
            unsigned hi[8], lo[8];
            float wv[16] = {wr0.x, wr0.y, wr0.z, wr0.w, wr1.x, wr1.y, wr1.z, wr1.w,
                            wr2.x, wr2.y, wr2.z, wr2.w, wr3.x, wr3.y, wr3.z, wr3.w};
            #pragma unroll
            for (int i = 0; i < 8; i++)
                split2(wv[2 * i] * winvs, wv[2 * i + 1] * winvs, hi[i], lo[i]);
            char* dh = base + wrow * 80 + wcol * 2;
            *(uint4*)(dh)      = *(uint4*)(hi);
            *(uint4*)(dh + 16) = *(uint4*)(hi + 4);
            char* dl = dh + 15360;
            *(uint4*)(dl)      = *(uint4*)(lo);
            *(uint4*)(dl + 16) = *(uint4*)(lo + 4);
        }
        if (t < 256) {
            unsigned hi[8], lo[8];
            float xv[16] = {xr0.x, xr0.y, xr0.z, xr0.w, xr1.x, xr1.y, xr1.z, xr1.w,
                            xr2.x, xr2.y, xr2.z, xr2.w, xr3.x, xr3.y, xr3.z, xr3.w};
            #pragma unroll
            for (int i = 0; i < 8; i++)
                split2(xv[2 * i], xv[2 * i + 1], hi[i], lo[i]);
            char* dh = base + 30720 + xrow * 272 + xcol * 2;
            *(uint4*)(dh)      = *(uint4*)(hi);
            *(uint4*)(dh + 16) = *(uint4*)(hi + 4);
            char* dl = dh + 8704;
            *(uint4*)(dl)      = *(uint4*)(lo);
            *(uint4*)(dl + 16) = *(uint4*)(lo + 4);
        }
    };

    float D[2][8][4];
    #pragma unroll
    for (int mi = 0; mi < 2; mi++)
        #pragma unroll
        for (int nt = 0; nt < 8; nt++)
            #pragma unroll
            for (int r = 0; r < 4; r++) D[mi][nt][r] = 0.f;

    auto compute_chunk = [&](int sel) {
        unsigned sbase = sm_base + sel * FG_BUF;
        #pragma unroll
        for (int ks = 0; ks < 2; ks++) {
            unsigned ah[2][4], al[2][4];
            #pragma unroll
            for (int mi = 0; mi < 2; mi++) {
                unsigned aoff = sbase + ((wm * 32 + mi * 16 + ln15) * 40 + ks * 16 + lnh * 8) * 2;
                ldsm4(ah[mi], aoff);
                ldsm4(al[mi], aoff + 15360);
            }
            #pragma unroll
            for (int nt = 0; nt < 8; nt++) {
                unsigned boff = sbase + 30720 + ((ks * 16 + ln15) * 136 + wn * 64 + nt * 8) * 2;
                unsigned bh0, bh1, bl0, bl1;
                ldsm2t(bh0, bh1, boff);
                ldsm2t(bl0, bl1, boff + 8704);
                #pragma unroll
                for (int mi = 0; mi < 2; mi++) {
                    mma_bf16(D[mi][nt], ah[mi], bh0, bh1);
                    mma_bf16(D[mi][nt], al[mi], bh0, bh1);
                    mma_bf16(D[mi][nt], ah[mi], bl0, bl1);
                }
            }
        }
    };

    ldg_chunk(0);
    sts_chunk(0);
    __syncthreads();
    for (int c = 0; c < 16; c++) {
        if (c + 1 < 16) ldg_chunk(c + 1);
        compute_chunk(c & 1);
        if (c + 1 < 16) sts_chunk((c + 1) & 1);
        __syncthreads();
    }

    int mat = wm >> 1;
    const float* bias = (mat == 0) ? bf : (mat == 1) ? bg : bh;
    #pragma unroll
    for (int mi = 0; mi < 2; mi++)
        #pragma unroll
        for (int rh = 0; rh < 2; rh++) {
            int kloc = (wm & 1) * 32 + mi * 16 + g + rh * 8;
            float bi = bias[kloc];
            size_t u32row = ((size_t)b * HCDIM + kloc) * (NSEQ / 2) + n0 / 2 + wn * 32 + tig;
            if (mat < 2) {
                unsigned* outh = (unsigned*)((mat == 0) ? d_fh : d_gh) + u32row;
                unsigned* outl = (unsigned*)((mat == 0) ? d_fl : d_gl) + u32row;
                #pragma unroll
                for (int nt = 0; nt < 8; nt++) {
                    unsigned hi, lo;
                    split2(D[mi][nt][2 * rh] + bi, D[mi][nt][2 * rh + 1] + bi, hi, lo);
                    outh[nt * 4] = hi;
                    outl[nt * 4] = lo;
                }
            } else {
                unsigned* outh = (unsigned*)d_hbf + u32row;
                #pragma unroll
                for (int nt = 0; nt < 8; nt++)
                    outh[nt * 4] = pk_bf16(D[mi][nt][2 * rh] + bi, D[mi][nt][2 * rh + 1] + bi);
            }
        }
}

// ---------------- flash attention: split-m warp groups ----------------
// 8 warps = 4 q-blocks (32 q each) x 2 m-halves (64 m each). Independent online
// softmax per m-half; merged once at the end (split-K softmax merge).
// buf: gh[64][136u16] @0, gl @17408, h @34816. 2 bufs.
#define AT_BUF   52224
#define AT_TOTAL (2 * AT_BUF)
__global__ __launch_bounds__(256, 1) void attn_mma_kernel() {
    extern __shared__ char asm_[];
    int b  = blockIdx.y;
    int q0 = blockIdx.x * 128;
    int t  = threadIdx.x;
    int w    = t >> 5;
    int lane = t & 31;
    int qg   = w & 3;          // q block: rows qg*32 .. +32
    int mh   = w >> 2;         // m half: cols mh*64 .. +64
    int g    = lane >> 2;
    int tig  = lane & 3;
    int ln15 = lane & 15;

    const __nv_bfloat16* fhb = d_fh  + (size_t)b * HCDIM * NSEQ;
    const __nv_bfloat16* flb = d_fl  + (size_t)b * HCDIM * NSEQ;
    const __nv_bfloat16* ghb = d_gh  + (size_t)b * HCDIM * NSEQ;
    const __nv_bfloat16* glb = d_gl  + (size_t)b * HCDIM * NSEQ;
    const __nv_bfloat16* hb  = d_hbf + (size_t)b * HCDIM * NSEQ;

    // ---- stage f hi/lo into buf0, build A fragments (2 m-frags of 16 q) ----
    {
        #pragma unroll
        for (int u = t, i = 0; i < 4; i++, u += 256) {
            int r = u >> 4, c = u & 15;
            cp_async16(asm_ + r * 272 + c * 16,         fhb + (size_t)r * NSEQ + q0 + c * 8);
            cp_async16(asm_ + 17408 + r * 272 + c * 16, flb + (size_t)r * NSEQ + q0 + c * 8);
        }
        cp_commit();
        cp_wait<0>();
        __syncthreads();
    }
    unsigned afh[2][4][4], afl[2][4][4];
    {
        const __nv_bfloat16* fh = (const __nv_bfloat16*)asm_;
        const __nv_bfloat16* fl = (const __nv_bfloat16*)(asm_ + 17408);
        #pragma unroll
        for (int mi = 0; mi < 2; mi++) {
            int qb = qg * 32 + mi * 16;
            #pragma unroll
            for (int ks = 0; ks < 4; ks++) {
                int k0 = ks * 16 + 2 * tig;
                const __nv_bfloat16 *h0 = fh + k0 * 136, *h1 = fh + (k0 + 1) * 136;
                const __nv_bfloat16 *h2 = fh + (k0 + 8) * 136, *h3 = fh + (k0 + 9) * 136;
                afh[mi][ks][0] = pack2(h0 + qb + g,     h1 + qb + g);
                afh[mi][ks][1] = pack2(h0 + qb + g + 8, h1 + qb + g + 8);
                afh[mi][ks][2] = pack2(h2 + qb + g,     h3 + qb + g);
                afh[mi][ks][3] = pack2(h2 + qb + g + 8, h3 + qb + g + 8);
                const __nv_bfloat16 *l0p = fl + k0 * 136, *l1p = fl + (k0 + 1) * 136;
                const __nv_bfloat16 *l2p = fl + (k0 + 8) * 136, *l3p = fl + (k0 + 9) * 136;
                afl[mi][ks][0] = pack2(l0p + qb + g,     l1p + qb + g);
                afl[mi][ks][1] = pack2(l0p + qb + g + 8, l1p + qb + g + 8);
                afl[mi][ks][2] = pack2(l2p + qb + g,     l3p + qb + g);
                afl[mi][ks][3] = pack2(l2p + qb + g + 8, l3p + qb + g + 8);
            }
        }
    }
    __syncthreads();

    auto prefetch = [&](int mt, int sel) {
        char* gd = asm_ + sel * AT_BUF;
        int m0 = mt * 128;
        #pragma unroll
        for (int u = t, i = 0; i < 4; i++, u += 256) {
            int r = u >> 4, c = u & 15;
            cp_async16(gd + r * 272 + c * 16,         ghb + (size_t)r * NSEQ + m0 + c * 8);
            cp_async16(gd + 17408 + r * 272 + c * 16, glb + (size_t)r * NSEQ + m0 + c * 8);
            cp_async16(gd + 34816 + r * 272 + c * 16, hb  + (size_t)r * NSEQ + m0 + c * 8);
        }
        cp_commit();
    };

    float o[2][8][4];
    #pragma unroll
    for (int mi = 0; mi < 2; mi++)
        #pragma unroll
        for (int j = 0; j < 8; j++)
            #pragma unroll
            for (int i = 0; i < 4; i++) o[mi][j][i] = 0.f;
    float mr[2][2] = {{-1e30f, -1e30f}, {-1e30f, -1e30f}};
    float lr[2][2] = {{0.f, 0.f}, {0.f, 0.f}};

    prefetch(0, 0);
    prefetch(1, 1);

    for (int mt = 0; mt < NSEQ / 128; mt++) {
        if (mt < NSEQ / 128 - 1) cp_wait<1>(); else cp_wait<0>();
        __syncthreads();
        unsigned sbase = smem_u32(asm_) + (mt & 1) * AT_BUF;

        // ---- S = f^T g over this warp's 64-m half (split-bf16, 3-product) ----
        float st[2][8][4];
        #pragma unroll
        for (int mi = 0; mi < 2; mi++)
            #pragma unroll
            for (int nt = 0; nt < 8; nt++)
                #pragma unroll
                for (int i = 0; i < 4; i++) st[mi][nt][i] = 0.f;

        #pragma unroll
        for (int ks = 0; ks < 4; ks++) {
            unsigned rowoff = sbase + (ks * 16 + ln15) * 272 + mh * 128;
            #pragma unroll
            for (int nt = 0; nt < 8; nt++) {
                unsigned boff = rowoff + nt * 16;
                unsigned bh0, bh1, bl0, bl1;
                ldsm2t(bh0, bh1, boff);
                ldsm2t(bl0, bl1, boff + 17408);
                #pragma unroll
                for (int mi = 0; mi < 2; mi++) {
                    mma_bf16(st[mi][nt], afh[mi][ks], bh0, bh1);
                    mma_bf16(st[mi][nt], afl[mi][ks], bh0, bh1);
                    mma_bf16(st[mi][nt], afh[mi][ks], bl0, bl1);
                }
            }
        }

        // ---- online softmax (per m-frag, over this warp's 64 m-cols) ----
        #pragma unroll
        for (int mi = 0; mi < 2; mi++) {
            float mx0 = -1e30f, mx1 = -1e30f;
            #pragma unroll
            for (int nt = 0; nt < 8; nt++) {
                mx0 = fmaxf(mx0, fmaxf(st[mi][nt][0], st[mi][nt][1]));
                mx1 = fmaxf(mx1, fmaxf(st[mi][nt][2], st[mi][nt][3]));
            }
            mx0 = fmaxf(mx0, __shfl_xor_sync(0xffffffffu, mx0, 1));
            mx0 = fmaxf(mx0, __shfl_xor_sync(0xffffffffu, mx0, 2));
            mx1 = fmaxf(mx1, __shfl_xor_sync(0xffffffffu, mx1, 1));
            mx1 = fmaxf(mx1, __shfl_xor_sync(0xffffffffu, mx1, 2));

            float mn0 = fmaxf(mr[mi][0], mx0), mn1 = fmaxf(mr[mi][1], mx1);
            float sc0 = __expf(mr[mi][0] - mn0), sc1 = __expf(mr[mi][1] - mn1);
            mr[mi][0] = mn0; mr[mi][1] = mn1;

            float rs0 = 0.f, rs1 = 0.f;
            #pragma unroll
            for (int nt = 0; nt < 8; nt++) {
                st[mi][nt][0] = __expf(st[mi][nt][0] - mn0);
                st[mi][nt][1] = __expf(st[mi][nt][1] - mn0);
                st[mi][nt][2] = __expf(st[mi][nt][2] - mn1);
                st[mi][nt][3] = __expf(st[mi][nt][3] - mn1);
                rs0 += st[mi][nt][0] + st[mi][nt][1];
                rs1 += st[mi][nt][2] + st[mi][nt][3];
            }
            rs0 += __shfl_xor_sync(0xffffffffu, rs0, 1);
            rs0 += __shfl_xor_sync(0xffffffffu, rs0, 2);
            rs1 += __shfl_xor_sync(0xffffffffu, rs1, 1);
            rs1 += __shfl_xor_sync(0xffffffffu, rs1, 2);
            lr[mi][0] = lr[mi][0] * sc0 + rs0;
            lr[mi][1] = lr[mi][1] * sc1 + rs1;

            #pragma unroll
            for (int j = 0; j < 8; j++) {
                o[mi][j][0] *= sc0; o[mi][j][1] *= sc0;
                o[mi][j][2] *= sc1; o[mi][j][3] *= sc1;
            }
        }

        // ---- O += P @ h over this warp's 64-m half ----
        unsigned hrow = sbase + 34816 + mh * 128;
        #pragma unroll
        for (int mi = 0; mi < 2; mi++) {
            #pragma unroll
            for (int kb = 0; kb < 4; kb++) {
                unsigned pa[4];
                pa[0] = pk_bf16(st[mi][2 * kb][0],     st[mi][2 * kb][1]);
                pa[1] = pk_bf16(st[mi][2 * kb][2],     st[mi][2 * kb][3]);
                pa[2] = pk_bf16(st[mi][2 * kb + 1][0], st[mi][2 * kb + 1][1]);
                pa[3] = pk_bf16(st[mi][2 * kb + 1][2], st[mi][2 * kb + 1][3]);
                #pragma unroll
                for (int jp = 0; jp < 4; jp++) {
                    unsigned haddr = hrow +
                        (jp * 16 + ((lane >> 4) << 3) + (lane & 7)) * 272 +
                        kb * 32 + ((lane >> 3) & 1) * 16;
                    unsigned hr[4];
                    ldsm4(hr, haddr);
                    mma_bf16(o[mi][2 * jp],     pa, hr[0], hr[1]);
                    mma_bf16(o[mi][2 * jp + 1], pa, hr[2], hr[3]);
                }
            }
        }
        __syncthreads();
        if (mt + 2 < NSEQ / 128) prefetch(mt + 2, mt & 1);
    }

    // ---- merge the two m-half states (split-K softmax merge) ----
    // layout over buffer space: soA[64][132] f32, soB[64][132], smx[2][128], slx[2][128], sfa/sfb[128]
    float* soA = (float*)asm_;
    float* soB = soA + 64 * 132;
    float* smx = soB + 64 * 132;
    float* slx = smx + 256;
    float* sfa = slx + 256;
    float* sfb = sfa + 128;

    float* so = mh ? soB : soA;
    #pragma unroll
    for (int mi = 0; mi < 2; mi++) {
        int qb = qg * 32 + mi * 16;
        #pragma unroll
        for (int j = 0; j < 8; j++) {
            int d = j * 8 + 2 * tig;
            so[d * 132 + qb + g]           = o[mi][j][0];
            so[(d + 1) * 132 + qb + g]     = o[mi][j][1];
            so[d * 132 + qb + g + 8]       = o[mi][j][2];
            so[(d + 1) * 132 + qb + g + 8] = o[mi][j][3];
        }
        if (tig == 0) {
            smx[mh * 128 + qb + g]     = mr[mi][0];
            smx[mh * 128 + qb + g + 8] = mr[mi][1];
            slx[mh * 128 + qb + g]     = lr[mi][0];
            slx[mh * 128 + qb + g + 8] = lr[mi][1];
        }
    }
    __syncthreads();
    if (t < 128) {
        float ma = smx[t], mbv = smx[128 + t];
        float ms = fmaxf(ma, mbv);
        float ea = __expf(ma - ms), eb = __expf(mbv - ms);
        float lsum = slx[t] * ea + slx[128 + t] * eb;
        float linv = 1.f / lsum;
        sfa[t] = ea * linv;
        sfb[t] = eb * linv;
    }
    __syncthreads();

    unsigned* ohp = (unsigned*)d_oh + (size_t)b * HCDIM * (NSEQ / 2);
    unsigned* olp = (unsigned*)d_ol + (size_t)b * HCDIM * (NSEQ / 2);
    for (int idx = t; idx < 64 * 64; idx += 256) {
        int d = idx >> 6, qq = (idx & 63) * 2;
        float a0 = soA[d * 132 + qq]     * sfa[qq]     + soB[d * 132 + qq]     * sfb[qq];
        float a1 = soA[d * 132 + qq + 1] * sfa[qq + 1] + soB[d * 132 + qq + 1] * sfb[qq + 1];
        unsigned hi, lo;
        split2(a0, a1, hi, lo);
        size_t half = (size_t)d * (NSEQ / 2) + (q0 + qq) / 2;
        ohp[half] = hi;
        olp[half] = lo;
    }
}

// ---------------- out = gamma * ((Wv/sigma) @ o + bv) + x  (split-bf16 MMA) ----------------
__global__ __launch_bounds__(256) void vproj_mma_kernel(
    const float* __restrict__ Wv, const float* __restrict__ bv,
    const float* __restrict__ x,  const float* __restrict__ gamma,
    float* __restrict__ out) {
    extern __shared__ char vsm[];
    char* sWh = vsm;
    char* sWl = vsm + 18432;
    char* sOh = vsm + 36864;
    char* sOl = vsm + 54272;

    int n0 = blockIdx.x * 128, c0 = blockIdx.y * 128, b = blockIdx.z;
    float invs = d_sig[3];
    int t = threadIdx.x, w = t >> 5, lane = t & 31;
    int wm = w & 3, wn = w >> 2;
    int g = lane >> 2, tig = lane & 3, ln15 = lane & 15, lnh = lane >> 4;

    {
        const __nv_bfloat16* oh = d_oh + (size_t)b * HCDIM * NSEQ;
        const __nv_bfloat16* ol = d_ol + (size_t)b * HCDIM * NSEQ;
        #pragma unroll
        for (int u = t, i = 0; i < 4; i++, u += 256) {
            int r = u >> 4, c = u & 15;
            cp_async16(sOh + r * 272 + c * 16, oh + (size_t)r * NSEQ + n0 + c * 8);
            cp_async16(sOl + r * 272 + c * 16, ol + (size_t)r * NSEQ + n0 + c * 8);
        }
        cp_commit();
    }
    {
        int row = t >> 1, kq = (t & 1) * 32;
        const float* wp = Wv + (size_t)(c0 + row) * HCDIM + kq;
        unsigned hi[16], lo[16];
        #pragma unroll
        for (int i2 = 0; i2 < 8; i2++) {
            float4 v4 = *(const float4*)(wp + i2 * 4);
            split2(v4.x * invs, v4.y * invs, hi[2 * i2],     lo[2 * i2]);
            split2(v4.z * invs, v4.w * invs, hi[2 * i2 + 1], lo[2 * i2 + 1]);
        }
        char* dh = sWh + row * 144 + kq * 2;
        char* dl = sWl + row * 144 + kq * 2;
        #pragma unroll
        for (int c = 0; c < 4; c++) {
            *(uint4*)(dh + c * 16) = *(uint4*)(hi + 4 * c);
            *(uint4*)(dl + c * 16) = *(uint4*)(lo + 4 * c);
        }
    }
    cp_wait<0>();
    __syncthreads();

    float D[2][8][4];
    #pragma unroll
    for (int mi = 0; mi < 2; mi++)
        #pragma unroll
        for (int nt = 0; nt < 8; nt++)
            #pragma unroll
            for (int r = 0; r < 4; r++) D[mi][nt][r] = 0.f;

    unsigned wbase = smem_u32(sWh);
    unsigned obase = smem_u32(sOh);
    #pragma unroll
    for (int ks = 0; ks < 4; ks++) {
        unsigned ah[2][4], al[2][4];
        #pragma unroll
        for (int mi = 0; mi < 2; mi++) {
            unsigned aoff = wbase + ((wm * 32 + mi * 16 + ln15) * 72 + ks * 16 + lnh * 8) * 2;
            ldsm4(ah[mi], aoff);
            ldsm4(al[mi], aoff + 18432);
        }
        #pragma unroll
        for (int nt = 0; nt < 8; nt++) {
            unsigned boff = obase + ((ks * 16 + ln15) * 136 + wn * 64 + nt * 8) * 2;
            unsigned bh0, bh1, bl0, bl1;
            ldsm2t(bh0, bh1, boff);
            ldsm2t(bl0, bl1, boff + 17408);
            #pragma unroll
            for (int mi = 0; mi < 2; mi++) {
                mma_bf16(D[mi][nt], ah[mi], bh0, bh1);
                mma_bf16(D[mi][nt], al[mi], bh0, bh1);
                mma_bf16(D[mi][nt], ah[mi], bl0, bl1);
            }
        }
    }

    float gm = gamma[0];
    #pragma unroll
    for (int mi = 0; mi < 2; mi++)
        #pragma unroll
        for (int rh = 0; rh < 2; rh++) {
            int c = c0 + wm * 32 + mi * 16 + g + rh * 8;
            float bi = bv[c];
            size_t base = ((size_t)b * CDIM + c) * NSEQ + n0 + wn * 64 + 2 * tig;
            #pragma unroll
            for (int nt = 0; nt < 8; nt++) {
                float2 xv = *(const float2*)(x + base + nt * 8);
                float2 r;
                r.x = gm * (D[mi][nt][2 * rh] + bi) + xv.x;
                r.y = gm * (D[mi][nt][2 * rh + 1] + bi) + xv.y;
                *(float2*)(out + base + nt * 8) = r;
            }
        }
}

// ---------------- launch ----------------
extern "C" void kernel_launch(void* const* d_in, const int* in_sizes, int n_in,
                              void* d_out, int out_size) {
    const float* x     = (const float*)d_in[0];
    const float* Wf    = (const float*)d_in[1];
    const float* bf    = (const float*)d_in[2];
    const float* Wg    = (const float*)d_in[3];
    const float* bg    = (const float*)d_in[4];
    const float* Wh    = (const float*)d_in[5];
    const float* bh    = (const float*)d_in[6];
    const float* Wv    = (const float*)d_in[7];
    const float* bv    = (const float*)d_in[8];
    const float* uf    = (const float*)d_in[9];
    const float* ug    = (const float*)d_in[10];
    const float* uh    = (const float*)d_in[11];
    const float* uv    = (const float*)d_in[12];
    const float* gamma = (const float*)d_in[13];
    float* out = (float*)d_out;

    const int FGH_SMEM  = 2 * FG_BUF;    // 96256
    const int ATTN_SMEM = AT_TOTAL;      // 104448
    const int VP_SMEM   = 71680;
    cudaFuncSetAttribute(attn_mma_kernel,  cudaFuncAttributeMaxDynamicSharedMemorySize, ATTN_SMEM);
    cudaFuncSetAttribute(fgh_mma_kernel,   cudaFuncAttributeMaxDynamicSharedMemorySize, FGH_SMEM);
    cudaFuncSetAttribute(vproj_mma_kernel, cudaFuncAttributeMaxDynamicSharedMemorySize, VP_SMEM);

    sigma_kernel<<<4, 256>>>(Wf, Wg, Wh, Wv, uf, ug, uh, uv);
    fgh_mma_kernel<<<dim3(NSEQ / 128, BATCH), 384, FGH_SMEM>>>(x, Wf, bf, Wg, bg, Wh, bh);
    attn_mma_kernel<<<dim3(NSEQ / 128, BATCH), 256, ATTN_SMEM>>>();
    vproj_mma_kernel<<<dim3(NSEQ / 128, CDIM / 128, BATCH), 256, VP_SMEM>>>(Wv, bv, x, gamma, out);
}

// round 11
// speedup vs baseline: 1.1354x; 1.1354x over previous
#include <cuda_runtime.h>
#include <cuda_bf16.h>
#include <math.h>

#define NSEQ  4096
#define CDIM  512
#define HCDIM 64
#define BATCH 4

// ---------------- scratch ----------------
__device__ float d_sig[4];
__device__ float d_fgh[2 * BATCH * HCDIM * NSEQ];            // f,g (f32) [mat][b][k][n]
__device__ __nv_bfloat16 d_hbf[BATCH * HCDIM * NSEQ];        // h  (bf16, scaled+bias)
__device__ __nv_bfloat16 d_oh [BATCH * HCDIM * NSEQ];        // o hi
__device__ __nv_bfloat16 d_ol [BATCH * HCDIM * NSEQ];        // o lo

// ---------------- small helpers ----------------
__device__ __forceinline__ unsigned to_tf32(float f) {
    unsigned r; asm("cvt.rna.tf32.f32 %0, %1;" : "=r"(r) : "f"(f)); return r;
}
__device__ __forceinline__ unsigned pk_bf16(float lo, float hi) {
    unsigned r; asm("cvt.rn.bf16x2.f32 %0, %1, %2;" : "=r"(r) : "f"(hi), "f"(lo)); return r;
}
__device__ __forceinline__ float ex2f(float x) {
    float r; asm("ex2.approx.f32 %0, %1;" : "=f"(r) : "f"(x)); return r;
}
__device__ __forceinline__ void mma_tf32(float* d, const unsigned* a, unsigned b0, unsigned b1) {
    asm volatile("mma.sync.aligned.m16n8k8.row.col.f32.tf32.tf32.f32 "
        "{%0,%1,%2,%3},{%4,%5,%6,%7},{%8,%9},{%0,%1,%2,%3};"
        : "+f"(d[0]), "+f"(d[1]), "+f"(d[2]), "+f"(d[3])
        : "r"(a[0]), "r"(a[1]), "r"(a[2]), "r"(a[3]), "r"(b0), "r"(b1));
}
__device__ __forceinline__ void mma_bf16(float* d, const unsigned* a, unsigned b0, unsigned b1) {
    asm volatile("mma.sync.aligned.m16n8k16.row.col.f32.bf16.bf16.f32 "
        "{%0,%1,%2,%3},{%4,%5,%6,%7},{%8,%9},{%0,%1,%2,%3};"
        : "+f"(d[0]), "+f"(d[1]), "+f"(d[2]), "+f"(d[3])
        : "r"(a[0]), "r"(a[1]), "r"(a[2]), "r"(a[3]), "r"(b0), "r"(b1));
}
__device__ __forceinline__ void ldsm4(unsigned* r, unsigned addr) {
    asm volatile("ldmatrix.sync.aligned.m8n8.x4.shared.b16 {%0,%1,%2,%3}, [%4];"
                 : "=r"(r[0]), "=r"(r[1]), "=r"(r[2]), "=r"(r[3]) : "r"(addr));
}
__device__ __forceinline__ void ldsm2t(unsigned& r0, unsigned& r1, unsigned addr) {
    asm volatile("ldmatrix.sync.aligned.m8n8.x2.trans.shared.b16 {%0,%1}, [%2];"
                 : "=r"(r0), "=r"(r1) : "r"(addr));
}
__device__ __forceinline__ unsigned smem_u32(const void* p) {
    return (unsigned)__cvta_generic_to_shared(p);
}
__device__ __forceinline__ void cp_async16(void* dst, const void* src) {
    asm volatile("cp.async.cg.shared.global [%0], [%1], 16;"
                 :: "r"(smem_u32(dst)), "l"(src));
}
__device__ __forceinline__ void cp_commit() { asm volatile("cp.async.commit_group;"); }
template <int N>
__device__ __forceinline__ void cp_wait() { asm volatile("cp.async.wait_group %0;" :: "n"(N)); }

__device__ __forceinline__ void split2(float a0, float a1, unsigned& hi, unsigned& lo) {
    hi = pk_bf16(a0, a1);
    __nv_bfloat162 hv = *reinterpret_cast<__nv_bfloat162*>(&hi);
    lo = pk_bf16(a0 - __bfloat162float(hv.x), a1 - __bfloat162float(hv.y));
}

// ---------------- spectral norm sigmas ----------------
__global__ void sigma_kernel(const float* __restrict__ Wf, const float* __restrict__ Wg,
                             const float* __restrict__ Wh, const float* __restrict__ Wv,
                             const float* __restrict__ uf, const float* __restrict__ ug,
                             const float* __restrict__ uh, const float* __restrict__ uv) {
    int mat = blockIdx.x;
    __shared__ float v[512];
    __shared__ float red[256];
    int t = threadIdx.x;

    if (mat < 3) {
        const float* W = (mat == 0) ? Wf : (mat == 1) ? Wg : Wh;
        const float* u = (mat == 0) ? uf : (mat == 1) ? ug : uh;
        for (int j = t; j < 512; j += 256) {
            float s = 0.f;
            #pragma unroll 8
            for (int i = 0; i < 64; i++) s += W[i * 512 + j] * u[i];
            v[j] = s;
        }
        __syncthreads();
        float ps = 0.f;
        for (int j = t; j < 512; j += 256) ps += v[j] * v[j];
        red[t] = ps; __syncthreads();
        for (int off = 128; off; off >>= 1) { if (t < off) red[t] += red[t + off]; __syncthreads(); }
        float inv = 1.f / fmaxf(sqrtf(red[0]), 1e-12f);
        __syncthreads();
        int i = t >> 2, q = t & 3;
        float s = 0.f;
        const float* wr = W + i * 512 + q * 128;
        const float* vv = v + q * 128;
        #pragma unroll 8
        for (int j = 0; j < 128; j += 4) {
            float4 w4 = *(const float4*)(wr + j);
            s += w4.x * vv[j] + w4.y * vv[j + 1] + w4.z * vv[j + 2] + w4.w * vv[j + 3];
        }
        s += __shfl_xor_sync(0xffffffffu, s, 1);
        s += __shfl_xor_sync(0xffffffffu, s, 2);
        s *= inv;
        red[t] = (q == 0) ? s * s : 0.f;
    } else {
        const float* W = Wv;
        const float* u = uv;
        int j = t & 63, ch = t >> 6;
        float s = 0.f;
        for (int i = ch * 128; i < ch * 128 + 128; i++) s += W[i * 64 + j] * u[i];
        red[t] = s; __syncthreads();
        if (t < 64) v[t] = red[t] + red[t + 64] + red[t + 128] + red[t + 192];
        __syncthreads();
        float ps = (t < 64) ? v[t] * v[t] : 0.f;
        __syncthreads();
        red[t] = ps; __syncthreads();
        for (int off = 128; off; off >>= 1) { if (t < off) red[t] += red[t + off]; __syncthreads(); }
        float inv = 1.f / fmaxf(sqrtf(red[0]), 1e-12f);
        __syncthreads();
        float ps2 = 0.f;
        #pragma unroll
        for (int rr = 0; rr < 2; rr++) {
            int i = t + rr * 256;
            float s2 = 0.f;
            const float* wr = W + i * 64;
            #pragma unroll
            for (int jj = 0; jj < 64; jj += 4) {
                float4 w4 = *(const float4*)(wr + jj);
                s2 += w4.x * v[jj] + w4.y * v[jj + 1] + w4.z * v[jj + 2] + w4.w * v[jj + 3];
            }
            s2 *= inv;
            ps2 += s2 * s2;
        }
        red[t] = ps2;
    }
    __syncthreads();
    for (int off = 128; off; off >>= 1) { if (t < off) red[t] += red[t + off]; __syncthreads(); }
    if (t == 0) d_sig[mat] = 1.f / fmaxf(sqrtf(red[0]), 1e-30f);
}

// ---------------- f,g,h = (W/sigma) @ x + b  (split-bf16 3-product MMA) ----------------
#define FGH_BUF 27648
__global__ __launch_bounds__(256) void fgh_mma_kernel(
    const float* __restrict__ x,
    const float* __restrict__ Wf, const float* __restrict__ bf,
    const float* __restrict__ Wg, const float* __restrict__ bg,
    const float* __restrict__ Wh, const float* __restrict__ bh) {
    extern __shared__ char fsm[];
    int n0 = blockIdx.x * 128;
    int mat = blockIdx.y;
    int b = blockIdx.z;
    const float* W    = (mat == 0) ? Wf : (mat == 1) ? Wg : Wh;
    const float* bias = (mat == 0) ? bf : (mat == 1) ? bg : bh;
    float invs = d_sig[mat];

    int t = threadIdx.x, w = t >> 5, lane = t & 31;
    int wm = w & 1, wn = w >> 1;
    int g = lane >> 2, tig = lane & 3, ln15 = lane & 15, lnh = lane >> 4;
    int wrow = t >> 2, wcol = (t & 3) * 8;
    int xrow = t >> 3, xcol = (t & 7) * 16;
    const float* xp = x + (size_t)b * CDIM * NSEQ;
    unsigned sm_base = smem_u32(fsm);

    float4 wr0, wr1, xr0, xr1, xr2, xr3;
    auto ldg_chunk = [&](int chunk) {
        int c0 = chunk * 32;
        const float* wp = W + wrow * 512 + c0 + wcol;
        wr0 = *(const float4*)(wp);
        wr1 = *(const float4*)(wp + 4);
        const float* xq = xp + (size_t)(c0 + xrow) * NSEQ + n0 + xcol;
        xr0 = *(const float4*)(xq);
        xr1 = *(const float4*)(xq + 4);
        xr2 = *(const float4*)(xq + 8);
        xr3 = *(const float4*)(xq + 12);
    };
    auto sts_chunk = [&](int sel) {
        char* base = fsm + sel * FGH_BUF;
        {
            unsigned hi[4], lo[4];
            float wv[8] = {wr0.x, wr0.y, wr0.z, wr0.w, wr1.x, wr1.y, wr1.z, wr1.w};
            #pragma unroll
            for (int i = 0; i < 4; i++)
                split2(wv[2 * i] * invs, wv[2 * i + 1] * invs, hi[i], lo[i]);
            *(uint4*)(base + wrow * 80 + wcol * 2)        = *(uint4*)hi;
            *(uint4*)(base + 5120 + wrow * 80 + wcol * 2) = *(uint4*)lo;
        }
        {
            unsigned hi[8], lo[8];
            float xv[16] = {xr0.x, xr0.y, xr0.z, xr0.w, xr1.x, xr1.y, xr1.z, xr1.w,
                            xr2.x, xr2.y, xr2.z, xr2.w, xr3.x, xr3.y, xr3.z, xr3.w};
            #pragma unroll
            for (int i = 0; i < 8; i++)
                split2(xv[2 * i], xv[2 * i + 1], hi[i], lo[i]);
            char* xh = base + 10240 + xrow * 272 + xcol * 2;
            char* xl = base + 18944 + xrow * 272 + xcol * 2;
            *(uint4*)(xh)      = *(uint4*)(hi);
            *(uint4*)(xh + 16) = *(uint4*)(hi + 4);
            *(uint4*)(xl)      = *(uint4*)(lo);
            *(uint4*)(xl + 16) = *(uint4*)(lo + 4);
        }
    };

    float D[2][4][4];
    #pragma unroll
    for (int mi = 0; mi < 2; mi++)
        #pragma unroll
        for (int nt = 0; nt < 4; nt++)
            #pragma unroll
            for (int r = 0; r < 4; r++) D[mi][nt][r] = 0.f;

    auto compute_chunk = [&](int sel) {
        unsigned sbase = sm_base + sel * FGH_BUF;
        #pragma unroll
        for (int ks = 0; ks < 2; ks++) {
            unsigned ah[2][4], al[2][4];
            #pragma unroll
            for (int mi = 0; mi < 2; mi++) {
                unsigned aoff = sbase + ((wm * 32 + mi * 16 + ln15) * 40 + ks * 16 + lnh * 8) * 2;
                ldsm4(ah[mi], aoff);
                ldsm4(al[mi], aoff + 5120);
            }
            #pragma unroll
            for (int nt = 0; nt < 4; nt++) {
                unsigned boff = sbase + 10240 + ((ks * 16 + ln15) * 136 + wn * 32 + nt * 8) * 2;
                unsigned bh0, bh1, bl0, bl1;
                ldsm2t(bh0, bh1, boff);
                ldsm2t(bl0, bl1, boff + 8704);
                #pragma unroll
                for (int mi = 0; mi < 2; mi++) {
                    mma_bf16(D[mi][nt], ah[mi], bh0, bh1);
                    mma_bf16(D[mi][nt], al[mi], bh0, bh1);
                    mma_bf16(D[mi][nt], ah[mi], bl0, bl1);
                }
            }
        }
    };

    ldg_chunk(0);
    sts_chunk(0);
    __syncthreads();
    for (int c = 0; c < 16; c++) {
        if (c + 1 < 16) ldg_chunk(c + 1);
        compute_chunk(c & 1);
        if (c + 1 < 16) sts_chunk((c + 1) & 1);
        __syncthreads();
    }

    if (mat < 2) {
        float* op = d_fgh + (size_t)(mat * BATCH + b) * HCDIM * NSEQ;
        #pragma unroll
        for (int mi = 0; mi < 2; mi++)
            #pragma unroll
            for (int rh = 0; rh < 2; rh++) {
                int k = wm * 32 + mi * 16 + g + rh * 8;
                float bi = bias[k];
                size_t rowbase = (size_t)k * NSEQ + n0 + wn * 32 + 2 * tig;
                #pragma unroll
                for (int nt = 0; nt < 4; nt++) {
                    float2 r;
                    r.x = D[mi][nt][2 * rh] + bi;
                    r.y = D[mi][nt][2 * rh + 1] + bi;
                    *(float2*)(op + rowbase + nt * 8) = r;
                }
            }
    } else {
        unsigned* hp = (unsigned*)d_hbf + (size_t)b * HCDIM * (NSEQ / 2);
        #pragma unroll
        for (int mi = 0; mi < 2; mi++)
            #pragma unroll
            for (int rh = 0; rh < 2; rh++) {
                int k = wm * 32 + mi * 16 + g + rh * 8;
                float bi = bias[k];
                size_t rowbase = (size_t)k * (NSEQ / 2) + (n0 + wn * 32) / 2 + tig;
                #pragma unroll
                for (int nt = 0; nt < 4; nt++)
                    hp[rowbase + nt * 4] =
                        pk_bf16(D[mi][nt][2 * rh] + bi, D[mi][nt][2 * rh + 1] + bi);
            }
    }
}

// ---------------- flash attention (tf32 S in log2-domain, bf16 PV, cp.async) ----------------
// smem: buf{0,1}: g f32 [64][136] (34816 B) + h bf16 [64][136] (17408 B)
#define AT_BUF   52224
#define AT_HOFF  34816
#define AT_TOTAL (2 * AT_BUF)
__global__ __launch_bounds__(256, 1) void attn_mma_kernel() {
    extern __shared__ char asm_[];
    int b  = blockIdx.y;
    int q0 = blockIdx.x * 128;
    int t  = threadIdx.x;
    int w    = t >> 5;
    int lane = t & 31;
    int g    = lane >> 2;
    int tig  = lane & 3;
    int qb   = w * 16;
    const float LOG2E = 1.4426950408889634f;

    const float* fbase = d_fgh + (size_t)(0 * BATCH + b) * HCDIM * NSEQ;
    const float* gbase = d_fgh + (size_t)(1 * BATCH + b) * HCDIM * NSEQ;
    const __nv_bfloat16* hbase = d_hbf + (size_t)b * HCDIM * NSEQ;

    // ---- stage f tile (f32) into buf0, build tf32 A fragments pre-scaled by log2(e) ----
    {
        char* fd = asm_;
        for (int u = t; u < 2048; u += 256) {
            int r = u >> 5, c = u & 31;
            cp_async16(fd + r * 544 + c * 16, fbase + (size_t)r * NSEQ + q0 + c * 4);
        }
        cp_commit();
        cp_wait<0>();
        __syncthreads();
    }
    unsigned af[8][4];
    {
        const float* fs = (const float*)asm_;
        #pragma unroll
        for (int ks = 0; ks < 8; ks++) {
            af[ks][0] = to_tf32(fs[(8 * ks + tig) * 136 + qb + g] * LOG2E);
            af[ks][1] = to_tf32(fs[(8 * ks + tig) * 136 + qb + g + 8] * LOG2E);
            af[ks][2] = to_tf32(fs[(8 * ks + tig + 4) * 136 + qb + g] * LOG2E);
            af[ks][3] = to_tf32(fs[(8 * ks + tig + 4) * 136 + qb + g + 8] * LOG2E);
        }
    }
    __syncthreads();

    auto prefetch = [&](int mt, int sel) {
        char* gd = asm_ + sel * AT_BUF;
        char* hd = gd + AT_HOFF;
        int m0 = mt * 128;
        #pragma unroll
        for (int u = t, i = 0; i < 8; i++, u += 256) {
            int r = u >> 5, c = u & 31;
            cp_async16(gd + r * 544 + c * 16, gbase + (size_t)r * NSEQ + m0 + c * 4);
        }
        #pragma unroll
        for (int u = t, i = 0; i < 4; i++, u += 256) {
            int r = u >> 4, c = u & 15;
            cp_async16(hd + r * 272 + c * 16, hbase + (size_t)r * NSEQ + m0 + c * 8);
        }
        cp_commit();
    };

    float o[8][4];
    #pragma unroll
    for (int j = 0; j < 8; j++)
        #pragma unroll
        for (int i = 0; i < 4; i++) o[j][i] = 0.f;
    float m0r = -1e30f, m1r = -1e30f, l0 = 0.f, l1 = 0.f;

    prefetch(0, 0);
    prefetch(1, 1);

    for (int mt = 0; mt < NSEQ / 128; mt++) {
        if (mt < NSEQ / 128 - 1) cp_wait<1>(); else cp_wait<0>();
        __syncthreads();
        const float*    sg = (const float*)(asm_ + (mt & 1) * AT_BUF);
        const unsigned* sh = (const unsigned*)(asm_ + (mt & 1) * AT_BUF + AT_HOFF);

        // ---- S' = log2e * f^T g (tf32, B = raw f32 bits) ----
        float st[16][4];
        #pragma unroll
        for (int nt = 0; nt < 16; nt++)
            #pragma unroll
            for (int i = 0; i < 4; i++) st[nt][i] = 0.f;

        #pragma unroll
        for (int ks = 0; ks < 8; ks++) {
            int r0 = (8 * ks + tig) * 136;
            int r1 = (8 * ks + tig + 4) * 136;
            #pragma unroll
            for (int nt = 0; nt < 16; nt++) {
                unsigned b0 = __float_as_uint(sg[r0 + nt * 8 + g]);
                unsigned b1 = __float_as_uint(sg[r1 + nt * 8 + g]);
                mma_tf32(st[nt], af[ks], b0, b1);
            }
        }

        // ---- online softmax (log2-domain scores, bare ex2) ----
        float mx0 = -1e30f, mx1 = -1e30f;
        #pragma unroll
        for (int nt = 0; nt < 16; nt++) {
            mx0 = fmaxf(mx0, fmaxf(st[nt][0], st[nt][1]));
            mx1 = fmaxf(mx1, fmaxf(st[nt][2], st[nt][3]));
        }
        mx0 = fmaxf(mx0, __shfl_xor_sync(0xffffffffu, mx0, 1));
        mx0 = fmaxf(mx0, __shfl_xor_sync(0xffffffffu, mx0, 2));
        mx1 = fmaxf(mx1, __shfl_xor_sync(0xffffffffu, mx1, 1));
        mx1 = fmaxf(mx1, __shfl_xor_sync(0xffffffffu, mx1, 2));

        float mn0 = fmaxf(m0r, mx0), mn1 = fmaxf(m1r, mx1);
        float sc0 = ex2f(m0r - mn0), sc1 = ex2f(m1r - mn1);
        m0r = mn0; m1r = mn1;

        float rs0 = 0.f, rs1 = 0.f;
        #pragma unroll
        for (int nt = 0; nt < 16; nt++) {
            st[nt][0] = ex2f(st[nt][0] - mn0);
            st[nt][1] = ex2f(st[nt][1] - mn0);
            st[nt][2] = ex2f(st[nt][2] - mn1);
            st[nt][3] = ex2f(st[nt][3] - mn1);
            rs0 += st[nt][0] + st[nt][1];
            rs1 += st[nt][2] + st[nt][3];
        }
        rs0 += __shfl_xor_sync(0xffffffffu, rs0, 1);
        rs0 += __shfl_xor_sync(0xffffffffu, rs0, 2);
        rs1 += __shfl_xor_sync(0xffffffffu, rs1, 1);
        rs1 += __shfl_xor_sync(0xffffffffu, rs1, 2);
        l0 = l0 * sc0 + rs0;
        l1 = l1 * sc1 + rs1;

        #pragma unroll
        for (int j = 0; j < 8; j++) {
            o[j][0] *= sc0; o[j][1] *= sc0;
            o[j][2] *= sc1; o[j][3] *= sc1;
        }

        // ---- O += P @ h ----
        #pragma unroll
        for (int kb = 0; kb < 8; kb++) {
            unsigned pa[4];
            pa[0] = pk_bf16(st[2 * kb][0],     st[2 * kb][1]);
            pa[1] = pk_bf16(st[2 * kb][2],     st[2 * kb][3]);
            pa[2] = pk_bf16(st[2 * kb + 1][0], st[2 * kb + 1][1]);
            pa[3] = pk_bf16(st[2 * kb + 1][2], st[2 * kb + 1][3]);
            #pragma unroll
            for (int j = 0; j < 8; j++) {
                unsigned hb0 = sh[(j * 8 + g) * 68 + kb * 8 + tig];
                unsigned hb1 = sh[(j * 8 + g) * 68 + kb * 8 + tig + 4];
                mma_bf16(o[j], pa, hb0, hb1);
            }
        }
        __syncthreads();
        if (mt + 2 < NSEQ / 128) prefetch(mt + 2, mt & 1);
    }

    // ---- normalize, stage [d][q] (f32) in buf0, write hi/lo bf16 ----
    float* sg = (float*)asm_;
    float li0 = 1.f / l0, li1 = 1.f / l1;
    #pragma unroll
    for (int j = 0; j < 8; j++) {
        int d = j * 8 + 2 * tig;
        sg[d * 136 + qb + g]           = o[j][0] * li0;
        sg[(d + 1) * 136 + qb + g]     = o[j][1] * li0;
        sg[d * 136 + qb + g + 8]       = o[j][2] * li1;
        sg[(d + 1) * 136 + qb + g + 8] = o[j][3] * li1;
    }
    __syncthreads();
    unsigned* ohp = (unsigned*)d_oh + (size_t)b * HCDIM * (NSEQ / 2);
    unsigned* olp = (unsigned*)d_ol + (size_t)b * HCDIM * (NSEQ / 2);
    for (int idx = t; idx < 64 * 32; idx += 256) {
        int d = idx >> 5, qq = (idx & 31) << 2;
        float4 v = *(const float4*)(sg + d * 136 + qq);
        unsigned h0, l0u, h1, l1u;
        split2(v.x, v.y, h0, l0u);
        split2(v.z, v.w, h1, l1u);
        size_t half = (size_t)d * (NSEQ / 2) + (q0 + qq) / 2;
        *(uint2*)(ohp + half) = make_uint2(h0, h1);
        *(uint2*)(olp + half) = make_uint2(l0u, l1u);
    }
}

// ---------------- out = gamma * ((Wv/sigma) @ o + bv) + x ----------------
// Merged over C: grid (32 n, 4 b), one CTA does all 4 c-chunks, o loaded once,
// W chunks register-prefetched during MMA.
__global__ __launch_bounds__(256) void vproj_mma_kernel(
    const float* __restrict__ Wv, const float* __restrict__ bv,
    const float* __restrict__ x,  const float* __restrict__ gamma,
    float* __restrict__ out) {
    extern __shared__ char vsm[];
    char* sWh = vsm;                 // [128][72] b16
    char* sWl = vsm + 18432;
    char* sOh = vsm + 36864;         // [64][136] b16
    char* sOl = vsm + 54272;

    int n0 = blockIdx.x * 128, b = blockIdx.y;
    float invs = d_sig[3];
    int t = threadIdx.x, w = t >> 5, lane = t & 31;
    int wm = w & 3, wn = w >> 2;
    int g = lane >> 2, tig = lane & 3, ln15 = lane & 15, lnh = lane >> 4;

    // ---- o tiles once: cp.async straight in (bf16 hi/lo) ----
    {
        const __nv_bfloat16* oh = d_oh + (size_t)b * HCDIM * NSEQ;
        const __nv_bfloat16* ol = d_ol + (size_t)b * HCDIM * NSEQ;
        #pragma unroll
        for (int u = t, i = 0; i < 4; i++, u += 256) {
            int r = u >> 4, c = u & 15;
            cp_async16(sOh + r * 272 + c * 16, oh + (size_t)r * NSEQ + n0 + c * 8);
            cp_async16(sOl + r * 272 + c * 16, ol + (size_t)r * NSEQ + n0 + c * 8);
        }
        cp_commit();
    }

    int row = t >> 1, kq = (t & 1) * 32;
    float4 wreg[8];
    auto ldgW = [&](int c0) {
        const float* wp = Wv + (size_t)(c0 + row) * HCDIM + kq;
        #pragma unroll
        for (int i = 0; i < 8; i++) wreg[i] = *(const float4*)(wp + i * 4);
    };
    auto stsW = [&]() {
        unsigned hi[16], lo[16];
        #pragma unroll
        for (int i2 = 0; i2 < 8; i2++) {
            split2(wreg[i2].x * invs, wreg[i2].y * invs, hi[2 * i2],     lo[2 * i2]);
            split2(wreg[i2].z * invs, wreg[i2].w * invs, hi[2 * i2 + 1], lo[2 * i2 + 1]);
        }
        char* dh = sWh + row * 144 + kq * 2;
        char* dl = sWl + row * 144 + kq * 2;
        #pragma unroll
        for (int c = 0; c < 4; c++) {
            *(uint4*)(dh + c * 16) = *(uint4*)(hi + 4 * c);
            *(uint4*)(dl + c * 16) = *(uint4*)(lo + 4 * c);
        }
    };

    ldgW(0);
    stsW();
    cp_wait<0>();
    __syncthreads();

    unsigned wbase = smem_u32(sWh);
    unsigned obase = smem_u32(sOh);
    float gm = gamma[0];

    for (int cc = 0; cc < 4; cc++) {
        int c0 = cc * 128;
        if (cc < 3) ldgW(c0 + 128);

        float D[2][8][4];
        #pragma unroll
        for (int mi = 0; mi < 2; mi++)
            #pragma unroll
            for (int nt = 0; nt < 8; nt++)
                #pragma unroll
                for (int r = 0; r < 4; r++) D[mi][nt][r] = 0.f;

        #pragma unroll
        for (int ks = 0; ks < 4; ks++) {
            unsigned ah[2][4], al[2][4];
            #pragma unroll
            for (int mi = 0; mi < 2; mi++) {
                unsigned aoff = wbase + ((wm * 32 + mi * 16 + ln15) * 72 + ks * 16 + lnh * 8) * 2;
                ldsm4(ah[mi], aoff);
                ldsm4(al[mi], aoff + 18432);
            }
            #pragma unroll
            for (int nt = 0; nt < 8; nt++) {
                unsigned boff = obase + ((ks * 16 + ln15) * 136 + wn * 64 + nt * 8) * 2;
                unsigned bh0, bh1, bl0, bl1;
                ldsm2t(bh0, bh1, boff);
                ldsm2t(bl0, bl1, boff + 17408);
                #pragma unroll
                for (int mi = 0; mi < 2; mi++) {
                    mma_bf16(D[mi][nt], ah[mi], bh0, bh1);
                    mma_bf16(D[mi][nt], al[mi], bh0, bh1);
                    mma_bf16(D[mi][nt], ah[mi], bl0, bl1);
                }
            }
        }

        #pragma unroll
        for (int mi = 0; mi < 2; mi++)
            #pragma unroll
            for (int rh = 0; rh < 2; rh++) {
                int c = c0 + wm * 32 + mi * 16 + g + rh * 8;
                float bi = bv[c];
                size_t base = ((size_t)b * CDIM + c) * NSEQ + n0 + wn * 64 + 2 * tig;
                #pragma unroll
                for (int nt = 0; nt < 8; nt++) {
                    float2 xv = *(const float2*)(x + base + nt * 8);
                    float2 r;
                    r.x = gm * (D[mi][nt][2 * rh] + bi) + xv.x;
                    r.y = gm * (D[mi][nt][2 * rh + 1] + bi) + xv.y;
                    *(float2*)(out + base + nt * 8) = r;
                }
            }

        __syncthreads();
        if (cc < 3) { stsW(); __syncthreads(); }
    }
}

// ---------------- launch ----------------
extern "C" void kernel_launch(void* const* d_in, const int* in_sizes, int n_in,
                              void* d_out, int out_size) {
    const float* x     = (const float*)d_in[0];
    const float* Wf    = (const float*)d_in[1];
    const float* bf    = (const float*)d_in[2];
    const float* Wg    = (const float*)d_in[3];
    const float* bg    = (const float*)d_in[4];
    const float* Wh    = (const float*)d_in[5];
    const float* bh    = (const float*)d_in[6];
    const float* Wv    = (const float*)d_in[7];
    const float* bv    = (const float*)d_in[8];
    const float* uf    = (const float*)d_in[9];
    const float* ug    = (const float*)d_in[10];
    const float* uh    = (const float*)d_in[11];
    const float* uv    = (const float*)d_in[12];
    const float* gamma = (const float*)d_in[13];
    float* out = (float*)d_out;

    const int FGH_SMEM  = 2 * FGH_BUF;   // 55296
    const int ATTN_SMEM = AT_TOTAL;      // 104448
    const int VP_SMEM   = 71680;
    cudaFuncSetAttribute(attn_mma_kernel,  cudaFuncAttributeMaxDynamicSharedMemorySize, ATTN_SMEM);
    cudaFuncSetAttribute(fgh_mma_kernel,   cudaFuncAttributeMaxDynamicSharedMemorySize, FGH_SMEM);
    cudaFuncSetAttribute(vproj_mma_kernel, cudaFuncAttributeMaxDynamicSharedMemorySize, VP_SMEM);

    sigma_kernel<<<4, 256>>>(Wf, Wg, Wh, Wv, uf, ug, uh, uv);
    fgh_mma_kernel<<<dim3(NSEQ / 128, 3, BATCH), 256, FGH_SMEM>>>(x, Wf, bf, Wg, bg, Wh, bh);
    attn_mma_kernel<<<dim3(NSEQ / 128, BATCH), 256, ATTN_SMEM>>>();
    vproj_mma_kernel<<<dim3(NSEQ / 128, BATCH), 256, VP_SMEM>>>(Wv, bv, x, gamma, out);
}